// round 9
// baseline (speedup 1.0000x reference)
#include <cuda_runtime.h>
#include <cuda_bf16.h>

#define NPTS 16384
#define KPB  4096
#define NKP  8192

typedef unsigned long long ull;

// ---------------- scratch (no cudaMalloc allowed) ----------------
__device__ float g_kpxyz[NKP * 3];
__device__ int   g_knni[NKP * 32];
__device__ float g_knnd[NKP * 32];
__device__ float g_pooled[NKP * 512];   // [kp][0:256)=scale_a, [256:512)=scale_b

// ---------------- packed f32x2 helpers ----------------
__device__ __forceinline__ ull fx2_add(ull a, ull b) { ull r; asm("add.rn.f32x2 %0,%1,%2;" : "=l"(r) : "l"(a), "l"(b)); return r; }
__device__ __forceinline__ ull fx2_mul(ull a, ull b) { ull r; asm("mul.rn.f32x2 %0,%1,%2;" : "=l"(r) : "l"(a), "l"(b)); return r; }
__device__ __forceinline__ ull fx2_fma(ull a, ull b, ull c) { ull r; asm("fma.rn.f32x2 %0,%1,%2,%3;" : "=l"(r) : "l"(a), "l"(b), "l"(c)); return r; }
__device__ __forceinline__ ull packf2(float lo, float hi) { ull r; asm("mov.b64 %0,{%1,%2};" : "=l"(r) : "f"(lo), "f"(hi)); return r; }
__device__ __forceinline__ void unpackf2(ull v, float& lo, float& hi) { asm("mov.b64 {%0,%1},%2;" : "=f"(lo), "=f"(hi) : "l"(v)); }

// ============================================================================
// 1. Furthest point sampling. One block per batch, 1024 threads.
//    Points in SMEM (192 KB), per-thread min-dists m[16] in registers.
//    Thread t owns point pairs {p*1024+t : p<8} -> points 2P, 2P+1.
//    argmax semantics: strictly-greater wins, ties -> lowest global index.
// ============================================================================
__global__ void __launch_bounds__(1024, 1) fps_kernel(const float* __restrict__ clouds) {
    extern __shared__ float sm[];
    float* sx = sm;
    float* sy = sm + NPTS;
    float* sz = sm + 2 * NPTS;
    __shared__ float s_pv[32];
    __shared__ int   s_pi[32];
    __shared__ float s_q[3];

    const int b = blockIdx.x;
    const float* cb = clouds + (size_t)b * 4 * NPTS;
    const int t = threadIdx.x;
    const int wid = t >> 5, lane = t & 31;

    for (int i = t; i < NPTS; i += 1024) {
        sx[i] = cb[i];
        sy[i] = cb[NPTS + i];
        sz[i] = cb[2 * NPTS + i];
    }
    if (t == 0) { s_q[0] = cb[0]; s_q[1] = cb[NPTS]; s_q[2] = cb[2 * NPTS]; }
    __syncthreads();

    float m[16];
#pragma unroll
    for (int i = 0; i < 16; i++) m[i] = 1e10f;

    float* kpx = g_kpxyz + (size_t)b * KPB * 3;
    const ull* sx2 = (const ull*)sx;
    const ull* sy2 = (const ull*)sy;
    const ull* sz2 = (const ull*)sz;

    for (int s = 0; s < KPB; s++) {
        float qx = s_q[0], qy = s_q[1], qz = s_q[2];
        if (t == 0) { kpx[s * 3] = qx; kpx[s * 3 + 1] = qy; kpx[s * 3 + 2] = qz; }

        ull nqx = packf2(-qx, -qx), nqy = packf2(-qy, -qy), nqz = packf2(-qz, -qz);
        float vmax = -1.0f;
        int vcode = 0;
#pragma unroll
        for (int p = 0; p < 8; p++) {
            int P = p * 1024 + t;
            ull X = sx2[P], Y = sy2[P], Z = sz2[P];
            ull dx = fx2_add(X, nqx);
            ull dy = fx2_add(Y, nqy);
            ull dz = fx2_add(Z, nqz);
            ull d2 = fx2_mul(dx, dx);
            d2 = fx2_fma(dy, dy, d2);
            d2 = fx2_fma(dz, dz, d2);
            float dlo, dhi;
            unpackf2(d2, dlo, dhi);
            m[2 * p]     = fminf(m[2 * p], dlo);
            m[2 * p + 1] = fminf(m[2 * p + 1], dhi);
            if (m[2 * p] > vmax)     { vmax = m[2 * p];     vcode = 2 * p; }
            if (m[2 * p + 1] > vmax) { vmax = m[2 * p + 1]; vcode = 2 * p + 1; }
        }
        int vi = ((vcode >> 1) << 11) + (t << 1) + (vcode & 1);

#pragma unroll
        for (int o = 16; o > 0; o >>= 1) {
            float ov = __shfl_down_sync(0xffffffffu, vmax, o);
            int   oi = __shfl_down_sync(0xffffffffu, vi, o);
            if (ov > vmax || (ov == vmax && oi < vi)) { vmax = ov; vi = oi; }
        }
        if (lane == 0) { s_pv[wid] = vmax; s_pi[wid] = vi; }
        __syncthreads();
        if (wid == 0) {
            float v = s_pv[lane];
            int i2 = s_pi[lane];
#pragma unroll
            for (int o = 16; o > 0; o >>= 1) {
                float ov = __shfl_down_sync(0xffffffffu, v, o);
                int   oi = __shfl_down_sync(0xffffffffu, i2, o);
                if (ov > v || (ov == v && oi < i2)) { v = ov; i2 = oi; }
            }
            if (lane == 0) { s_q[0] = sx[i2]; s_q[1] = sy[i2]; s_q[2] = sz[i2]; }
        }
        __syncthreads();
    }
}

// ============================================================================
// 2. Brute-force 32-NN. Thread-per-keypoint, register-resident worst-slot
//    replacement. Strict d < kmax keeps earlier index on ties (= top_k).
// ============================================================================
__global__ void __launch_bounds__(128) knn_kernel(const float* __restrict__ clouds) {
    __shared__ float sx[4096], sy[4096], sz[4096];
    const int kp = blockIdx.x * 128 + threadIdx.x;
    const int b = kp >> 12;
    const float* cb = clouds + (size_t)b * 4 * NPTS;
    const float kx = g_kpxyz[kp * 3], ky = g_kpxyz[kp * 3 + 1], kz = g_kpxyz[kp * 3 + 2];

    float bd[32];
    int bi[32];
#pragma unroll
    for (int j = 0; j < 32; j++) { bd[j] = 1e30f; bi[j] = 0; }
    float kmax = 1e30f;
    int kslot = 0;

    for (int tb = 0; tb < 4; tb++) {
        __syncthreads();
        for (int i = threadIdx.x; i < 4096; i += 128) {
            sx[i] = cb[tb * 4096 + i];
            sy[i] = cb[NPTS + tb * 4096 + i];
            sz[i] = cb[2 * NPTS + tb * 4096 + i];
        }
        __syncthreads();
#pragma unroll 4
        for (int i = 0; i < 4096; i++) {
            float dx = sx[i] - kx, dy = sy[i] - ky, dz = sz[i] - kz;
            float d = dx * dx;
            d = fmaf(dy, dy, d);
            d = fmaf(dz, dz, d);
            if (d < kmax) {
                int gi = tb * 4096 + i;
                float nk = -1.0f;
                int ns = 0;
#pragma unroll
                for (int j = 0; j < 32; j++) {
                    float v = (j == kslot) ? d : bd[j];
                    int   w = (j == kslot) ? gi : bi[j];
                    bd[j] = v;
                    bi[j] = w;
                    if (v > nk) { nk = v; ns = j; }
                }
                kmax = nk;
                kslot = ns;
            }
        }
    }
#pragma unroll
    for (int j = 0; j < 32; j++) {
        g_knnd[(size_t)kp * 32 + j] = bd[j];
        g_knni[(size_t)kp * 32 + j] = bi[j];
    }
}

// ============================================================================
// 3. PointNet MLP + masked max-pool per scale. Warp-per-keypoint.
//    W2 (128 KB) in SMEM; 4-sample x 8-channel register tile per lane.
//    NS==16: warp rank-filter selects the 16 smallest (d, idx) of the 32.
// ============================================================================
template <int NS>
__global__ void __launch_bounds__(256, 1) mlp_kernel(
    const float* __restrict__ clouds, const float* __restrict__ w1,
    const float* __restrict__ w2, float r2, int poff) {
    extern __shared__ float sm[];
    float* w2s = sm;                       // 32768
    float* w1s = sm + 32768;               // 512
    float* h1t = sm + 33280;               // 8*512
    float* sg  = sm + 33280 + 4096;        // 8*16
    float* sdd = sm + 33280 + 4096 + 128;  // 8*32
    int*   sii = (int*)(sm + 33280 + 4096 + 128 + 256);  // 8*32

    const int tid = threadIdx.x, wid = tid >> 5, lane = tid & 31;
    for (int i = tid; i < 8192; i += 256) ((float4*)w2s)[i] = ((const float4*)w2)[i];
    for (int i = tid; i < 512; i += 256) w1s[i] = w1[i];
    __syncthreads();

    float* mh1 = h1t + wid * 512;
    float* mg  = sg + wid * 16;
    float* msd = sdd + wid * 32;
    int*   msi = sii + wid * 32;

    float4 w1r0 = ((const float4*)w1s)[lane];
    float4 w1r1 = ((const float4*)w1s)[32 + lane];
    float4 w1r2 = ((const float4*)w1s)[64 + lane];
    float4 w1r3 = ((const float4*)w1s)[96 + lane];

    for (int kp = blockIdx.x * 8 + wid; kp < NKP; kp += gridDim.x * 8) {
        const int b = kp >> 12;
        const float* cb = clouds + (size_t)b * 4 * NPTS;
        float kx = g_kpxyz[kp * 3], ky = g_kpxyz[kp * 3 + 1], kz = g_kpxyz[kp * 3 + 2];

        // stage neighbor (d, idx) list into per-warp smem
        float nd = g_knnd[(size_t)kp * 32 + lane];
        int   ni = g_knni[(size_t)kp * 32 + lane];
        if (NS == 32) {
            msd[lane] = nd;
            msi[lane] = ni;
        } else {
            int rank = 0;
#pragma unroll
            for (int l = 0; l < 32; l++) {
                float dl = __shfl_sync(0xffffffffu, nd, l);
                int   il = __shfl_sync(0xffffffffu, ni, l);
                rank += (dl < nd) || (dl == nd && il < ni);
            }
            unsigned msk = __ballot_sync(0xffffffffu, rank < 16);
            int pos = __popc(msk & ((1u << lane) - 1u));
            if (rank < 16) { msd[pos] = nd; msi[pos] = ni; }
        }
        __syncwarp();

        float vmax[8];
#pragma unroll
        for (int c = 0; c < 8; c++) vmax[c] = 0.0f;

        for (int g0 = 0; g0 < NS; g0 += 4) {
            // gather 4 samples' features (lane<16: one component each)
            if (lane < 16) {
                int ss = lane >> 2, c = lane & 3;
                int idx = msi[g0 + ss];
                float val;
                if (c == 0) val = cb[idx] - kx;
                else if (c == 1) val = cb[NPTS + idx] - ky;
                else if (c == 2) val = cb[2 * NPTS + idx] - kz;
                else val = cb[3 * NPTS + idx];
                mg[ss * 4 + c] = val;
            }
            __syncwarp();

            // layer1: lane computes channels lane*4..lane*4+4 for 4 samples
            float hr[4][4];
#pragma unroll
            for (int ss = 0; ss < 4; ss++) {
                float4 g4 = ((const float4*)mg)[ss];
                float a0 = g4.x * w1r0.x; a0 = fmaf(g4.y, w1r1.x, a0); a0 = fmaf(g4.z, w1r2.x, a0); a0 = fmaf(g4.w, w1r3.x, a0);
                float a1 = g4.x * w1r0.y; a1 = fmaf(g4.y, w1r1.y, a1); a1 = fmaf(g4.z, w1r2.y, a1); a1 = fmaf(g4.w, w1r3.y, a1);
                float a2 = g4.x * w1r0.z; a2 = fmaf(g4.y, w1r1.z, a2); a2 = fmaf(g4.z, w1r2.z, a2); a2 = fmaf(g4.w, w1r3.z, a2);
                float a3 = g4.x * w1r0.w; a3 = fmaf(g4.y, w1r1.w, a3); a3 = fmaf(g4.z, w1r2.w, a3); a3 = fmaf(g4.w, w1r3.w, a3);
                hr[0][ss] = fmaxf(a0, 0.0f);
                hr[1][ss] = fmaxf(a1, 0.0f);
                hr[2][ss] = fmaxf(a2, 0.0f);
                hr[3][ss] = fmaxf(a3, 0.0f);
            }
#pragma unroll
            for (int c = 0; c < 4; c++)
                ((float4*)mh1)[lane * 4 + c] = make_float4(hr[c][0], hr[c][1], hr[c][2], hr[c][3]);
            __syncwarp();

            // layer2: lane owns channels {lane*4..+4} and {128+lane*4..+4}
            float acc[4][8];
#pragma unroll
            for (int ss = 0; ss < 4; ss++)
#pragma unroll
                for (int c = 0; c < 8; c++) acc[ss][c] = 0.0f;

#pragma unroll 4
            for (int k = 0; k < 128; k++) {
                float4 hv  = ((const float4*)mh1)[k];                 // samples 0..3 of h1[k]
                float4 wlo = ((const float4*)w2s)[k * 64 + lane];     // W2[k][lane*4..]
                float4 whi = ((const float4*)w2s)[k * 64 + 32 + lane];// W2[k][128+lane*4..]
                acc[0][0] = fmaf(hv.x, wlo.x, acc[0][0]); acc[0][1] = fmaf(hv.x, wlo.y, acc[0][1]);
                acc[0][2] = fmaf(hv.x, wlo.z, acc[0][2]); acc[0][3] = fmaf(hv.x, wlo.w, acc[0][3]);
                acc[0][4] = fmaf(hv.x, whi.x, acc[0][4]); acc[0][5] = fmaf(hv.x, whi.y, acc[0][5]);
                acc[0][6] = fmaf(hv.x, whi.z, acc[0][6]); acc[0][7] = fmaf(hv.x, whi.w, acc[0][7]);
                acc[1][0] = fmaf(hv.y, wlo.x, acc[1][0]); acc[1][1] = fmaf(hv.y, wlo.y, acc[1][1]);
                acc[1][2] = fmaf(hv.y, wlo.z, acc[1][2]); acc[1][3] = fmaf(hv.y, wlo.w, acc[1][3]);
                acc[1][4] = fmaf(hv.y, whi.x, acc[1][4]); acc[1][5] = fmaf(hv.y, whi.y, acc[1][5]);
                acc[1][6] = fmaf(hv.y, whi.z, acc[1][6]); acc[1][7] = fmaf(hv.y, whi.w, acc[1][7]);
                acc[2][0] = fmaf(hv.z, wlo.x, acc[2][0]); acc[2][1] = fmaf(hv.z, wlo.y, acc[2][1]);
                acc[2][2] = fmaf(hv.z, wlo.z, acc[2][2]); acc[2][3] = fmaf(hv.z, wlo.w, acc[2][3]);
                acc[2][4] = fmaf(hv.z, whi.x, acc[2][4]); acc[2][5] = fmaf(hv.z, whi.y, acc[2][5]);
                acc[2][6] = fmaf(hv.z, whi.z, acc[2][6]); acc[2][7] = fmaf(hv.z, whi.w, acc[2][7]);
                acc[3][0] = fmaf(hv.w, wlo.x, acc[3][0]); acc[3][1] = fmaf(hv.w, wlo.y, acc[3][1]);
                acc[3][2] = fmaf(hv.w, wlo.z, acc[3][2]); acc[3][3] = fmaf(hv.w, wlo.w, acc[3][3]);
                acc[3][4] = fmaf(hv.w, whi.x, acc[3][4]); acc[3][5] = fmaf(hv.w, whi.y, acc[3][5]);
                acc[3][6] = fmaf(hv.w, whi.z, acc[3][6]); acc[3][7] = fmaf(hv.w, whi.w, acc[3][7]);
            }

            // masked max-pool (vmax>=0, so skipping relu on acc is exact)
#pragma unroll
            for (int ss = 0; ss < 4; ss++) {
                if (msd[g0 + ss] < r2) {
#pragma unroll
                    for (int c = 0; c < 8; c++) vmax[c] = fmaxf(vmax[c], acc[ss][c]);
                }
            }
            __syncwarp();
        }

        float* pout = g_pooled + (size_t)kp * 512 + poff;
        ((float4*)pout)[lane] = make_float4(vmax[0], vmax[1], vmax[2], vmax[3]);
        ((float4*)(pout + 128))[lane] = make_float4(vmax[4], vmax[5], vmax[6], vmax[7]);
    }
}

// ============================================================================
// 4. Fuse GEMM: [8192,512] @ [512,128] + relu, plus keypoint coord writes.
//    Block = 128 threads (one per out channel) x 64 keypoints.
// ============================================================================
__global__ void __launch_bounds__(128) fuse_kernel(const float* __restrict__ wf,
                                                   float* __restrict__ out) {
    extern __shared__ float sp[];  // 64*512 floats
    const int tid = threadIdx.x;
    const int kp0 = blockIdx.x * 64;
    const float4* gp = (const float4*)(g_pooled + (size_t)kp0 * 512);
    for (int i = tid; i < 8192; i += 128) ((float4*)sp)[i] = gp[i];
    __syncthreads();

    float acc[64];
#pragma unroll
    for (int q = 0; q < 64; q++) acc[q] = 0.0f;

    for (int j0 = 0; j0 < 512; j0 += 4) {
        float wf0 = wf[(j0 + 0) * 128 + tid];
        float wf1 = wf[(j0 + 1) * 128 + tid];
        float wf2 = wf[(j0 + 2) * 128 + tid];
        float wf3 = wf[(j0 + 3) * 128 + tid];
#pragma unroll 16
        for (int q = 0; q < 64; q++) {
            float4 pv = ((const float4*)sp)[q * 128 + (j0 >> 2)];
            acc[q] = fmaf(pv.x, wf0, acc[q]);
            acc[q] = fmaf(pv.y, wf1, acc[q]);
            acc[q] = fmaf(pv.z, wf2, acc[q]);
            acc[q] = fmaf(pv.w, wf3, acc[q]);
        }
    }
    for (int q = 0; q < 64; q++) {
        int k = kp0 + q;
        out[(size_t)k * 131 + 3 + tid] = fmaxf(acc[q], 0.0f);
        if (tid < 3) out[(size_t)k * 131 + tid] = g_kpxyz[k * 3 + tid];
    }
}

// ============================================================================
extern "C" void kernel_launch(void* const* d_in, const int* in_sizes, int n_in,
                              void* d_out, int out_size) {
    const float* clouds = (const float*)d_in[0];
    const float* w1a = (const float*)d_in[1];
    const float* w2a = (const float*)d_in[2];
    const float* w1b = (const float*)d_in[3];
    const float* w2b = (const float*)d_in[4];
    const float* wfu = (const float*)d_in[5];
    float* out = (float*)d_out;

    const int fps_smem  = 3 * NPTS * 4;                                   // 196608
    const int mlp_smem  = (32768 + 512 + 4096 + 128 + 256 + 256) * 4;     // 152064
    const int fuse_smem = 64 * 512 * 4;                                   // 131072

    cudaFuncSetAttribute(fps_kernel, cudaFuncAttributeMaxDynamicSharedMemorySize, fps_smem);
    cudaFuncSetAttribute(mlp_kernel<16>, cudaFuncAttributeMaxDynamicSharedMemorySize, mlp_smem);
    cudaFuncSetAttribute(mlp_kernel<32>, cudaFuncAttributeMaxDynamicSharedMemorySize, mlp_smem);
    cudaFuncSetAttribute(fuse_kernel, cudaFuncAttributeMaxDynamicSharedMemorySize, fuse_smem);

    fps_kernel<<<2, 1024, fps_smem>>>(clouds);
    knn_kernel<<<64, 128>>>(clouds);
    mlp_kernel<16><<<148, 256, mlp_smem>>>(clouds, w1a, w2a, (float)(0.8 * 0.8), 0);
    mlp_kernel<32><<<148, 256, mlp_smem>>>(clouds, w1b, w2b, (float)(1.6 * 1.6), 256);
    fuse_kernel<<<128, 128, fuse_smem>>>(wfu, out);
}